// round 2
// baseline (speedup 1.0000x reference)
#include <cuda_runtime.h>
#include <math.h>

// Problem constants
#define FFT_N   16384            // next_pow2(L + K - 1)
#define FFT_HN  8192             // N/2, twiddle half-table size
#define L_IN    8192
#define K_FILT  8192
#define D_CH    256
#define B_SZ    8
#define TH      512              // threads per FFT CTA
#define NBUT    (FFT_N / 4)      // 4096 radix-4 butterflies per stage
#define START_OFF 4095           // (K-1)//2

// Padded shared-memory indexing to reduce bank conflicts on strided stages
#define SM_IDX(a) ((a) + ((a) >> 5))
#define SM_DATA_SZ (FFT_N + (FFT_N >> 5))            // 16896 float2
#define SMEM_BYTES ((SM_DATA_SZ + FFT_HN) * (int)sizeof(float2))  // 200704 B

// Scratch (device globals; allocation-free)
__device__ float2 g_tw[FFT_HN];                       // W_N^k, k in [0, N/2)
__device__ float2 g_Hf[(size_t)D_CH * FFT_N];         // filter spectra, digit-reversed, * (1/N)
__device__ float  g_ut[(size_t)B_SZ * D_CH * L_IN];   // row-major (B*D, L), reused for output

__device__ __forceinline__ float2 cadd(float2 a, float2 b){ return make_float2(a.x+b.x, a.y+b.y); }
__device__ __forceinline__ float2 csub(float2 a, float2 b){ return make_float2(a.x-b.x, a.y-b.y); }
__device__ __forceinline__ float2 cmul(float2 a, float2 b){
    return make_float2(a.x*b.x - a.y*b.y, a.x*b.y + a.y*b.x);
}
__device__ __forceinline__ float2 cmulc(float2 a, float2 b){   // a * conj(b)
    return make_float2(a.x*b.x + a.y*b.y, a.y*b.x - a.x*b.y);
}
// Half-table lookup: W_N^idx for idx in [0, 3N/4)
__device__ __forceinline__ float2 twget(const float2* __restrict__ tw, int idx){
    float2 w = tw[idx & (FFT_HN - 1)];
    if (idx & FFT_HN){ w.x = -w.x; w.y = -w.y; }
    return w;
}

// ---------------- FFT cores (in shared memory, in place) ----------------
// Forward: radix-4 DIF, 7 stages, natural -> base-4 digit-reversed order.
__device__ void fft_fwd(float2* __restrict__ d, const float2* __restrict__ tw){
    #pragma unroll
    for (int s = 0; s < 7; ++s){
        const int lq   = 12 - 2*s;        // log2(q), q = quarter of current block
        const int q    = 1 << lq;
        const int step = 1 << (2*s);      // N / m
        #pragma unroll
        for (int k = 0; k < NBUT/TH; ++k){
            int j    = threadIdx.x + k*TH;
            int i    = j & (q - 1);
            int base = ((j >> lq) << (lq + 2)) + i;
            float2 x0 = d[SM_IDX(base)];
            float2 x1 = d[SM_IDX(base +   q)];
            float2 x2 = d[SM_IDX(base + 2*q)];
            float2 x3 = d[SM_IDX(base + 3*q)];
            float2 t0 = cadd(x0, x2), t1 = csub(x0, x2);
            float2 t2 = cadd(x1, x3);
            float2 u  = csub(x1, x3);
            float2 t3 = make_float2(u.y, -u.x);        // -i * (x1 - x3)
            int iw = i * step;
            float2 y0 = cadd(t0, t2);
            float2 y1 = cmul(cadd(t1, t3), twget(tw, iw));
            float2 y2 = cmul(csub(t0, t2), twget(tw, 2*iw));
            float2 y3 = cmul(csub(t1, t3), twget(tw, 3*iw));
            d[SM_IDX(base)]       = y0;
            d[SM_IDX(base +   q)] = y1;
            d[SM_IDX(base + 2*q)] = y2;
            d[SM_IDX(base + 3*q)] = y3;
        }
        __syncthreads();
    }
}

// Inverse: radix-4 DIT, stages reversed, conjugate twiddles,
// digit-reversed -> natural order. 1/N folded into g_Hf.
__device__ void fft_inv(float2* __restrict__ d, const float2* __restrict__ tw){
    #pragma unroll
    for (int s = 6; s >= 0; --s){
        const int lq   = 12 - 2*s;
        const int q    = 1 << lq;
        const int step = 1 << (2*s);
        #pragma unroll
        for (int k = 0; k < NBUT/TH; ++k){
            int j    = threadIdx.x + k*TH;
            int i    = j & (q - 1);
            int base = ((j >> lq) << (lq + 2)) + i;
            float2 y0 = d[SM_IDX(base)];
            float2 y1 = d[SM_IDX(base +   q)];
            float2 y2 = d[SM_IDX(base + 2*q)];
            float2 y3 = d[SM_IDX(base + 3*q)];
            int iw = i * step;
            float2 u1 = cmulc(y1, twget(tw, iw));
            float2 u2 = cmulc(y2, twget(tw, 2*iw));
            float2 u3 = cmulc(y3, twget(tw, 3*iw));
            float2 a  = cadd(y0, u2), bb = csub(y0, u2);
            float2 cc = cadd(u1, u3), e  = csub(u1, u3);
            float2 ie = make_float2(-e.y, e.x);        // +i * (u1 - u3)
            d[SM_IDX(base)]       = cadd(a,  cc);
            d[SM_IDX(base +   q)] = cadd(bb, ie);
            d[SM_IDX(base + 2*q)] = csub(a,  cc);
            d[SM_IDX(base + 3*q)] = csub(bb, ie);
        }
        __syncthreads();
    }
}

// ---------------- Kernels ----------------
__global__ void twinit_kernel(){
    int k = blockIdx.x * blockDim.x + threadIdx.x;
    if (k < FFT_HN){
        double ang = -2.0 * M_PI * (double)k / (double)FFT_N;
        g_tw[k] = make_float2((float)cos(ang), (float)sin(ang));
    }
}

// One CTA per filter channel f: Hf[f] = DIF_FFT(pad(h[f])) * (1/N), digit-reversed order.
__global__ __launch_bounds__(TH) void filt_kernel(const float* __restrict__ h){
    extern __shared__ float2 sm[];
    float2* data = sm;
    float2* stw  = sm + SM_DATA_SZ;
    const int f = blockIdx.x;
    for (int k = threadIdx.x; k < FFT_HN; k += TH) stw[k] = g_tw[k];
    const float* hr = h + (size_t)f * K_FILT;
    for (int k = threadIdx.x; k < K_FILT; k += TH){
        data[SM_IDX(k)]          = make_float2(hr[k], 0.0f);
        data[SM_IDX(k + K_FILT)] = make_float2(0.0f, 0.0f);
    }
    __syncthreads();
    fft_fwd(data, stw);
    const float sc = 1.0f / (float)FFT_N;
    float2* Hrow = g_Hf + (size_t)f * FFT_N;
    for (int e = threadIdx.x; e < FFT_N; e += TH){
        float2 v = data[SM_IDX(e)];
        Hrow[e] = make_float2(v.x * sc, v.y * sc);
    }
}

// Input transpose: u(B,L,D) -> g_ut[(b*D + d)*L + l]   (reference row order r = b*D+d)
__global__ void tin_kernel(const float* __restrict__ u){
    __shared__ float tile[32][33];
    const int b  = blockIdx.z;
    const int l0 = blockIdx.x * 32, d0 = blockIdx.y * 32;
    const int tx = threadIdx.x, ty = threadIdx.y;
    tile[ty][tx] = u[(size_t)b * L_IN * D_CH + (size_t)(l0 + ty) * D_CH + d0 + tx];
    __syncthreads();
    // tile[tx][ty] = u[b][l0+tx][d0+ty]  -> row (b*D + d0+ty), pos l0+tx (coalesced in tx)
    g_ut[(size_t)(b * D_CH + d0 + ty) * L_IN + l0 + tx] = tile[tx][ty];
}

// Main fused conv: 1024 CTAs. CTA -> (batch b, channel pair d=2m, 2m+1).
// Reference filter mapping: row r = b*D + d uses H[r // B] = H[b*32 + d/8].
// Rows (b,2m) and (b,2m+1) share filter f = b*32 + (m>>2)  -> pack as one complex FFT.
__global__ __launch_bounds__(TH) void conv_kernel(){
    extern __shared__ float2 sm[];
    float2* data = sm;
    float2* stw  = sm + SM_DATA_SZ;
    const int c  = blockIdx.x;
    const int b  = c >> 7;                  // 0..7
    const int m  = c & 127;                 // channel pair index, d = 2m, 2m+1
    const int r0 = b * D_CH + 2*m;
    const int r1 = r0 + 1;
    const int f  = b * 32 + (m >> 2);       // shared filter index

    for (int k = threadIdx.x; k < FFT_HN; k += TH) stw[k] = g_tw[k];
    const float* x0 = g_ut + (size_t)r0 * L_IN;
    const float* x1 = g_ut + (size_t)r1 * L_IN;
    for (int k = threadIdx.x; k < L_IN; k += TH){
        data[SM_IDX(k)]        = make_float2(x0[k], x1[k]);   // pack two channels
        data[SM_IDX(k + L_IN)] = make_float2(0.0f, 0.0f);
    }
    __syncthreads();

    fft_fwd(data, stw);

    const float2* Hrow = g_Hf + (size_t)f * FFT_N;
    for (int e = threadIdx.x; e < FFT_N; e += TH){
        data[SM_IDX(e)] = cmul(data[SM_IDX(e)], Hrow[e]);     // same digit-reversed perm
    }
    __syncthreads();

    fft_inv(data, stw);

    float* y0 = g_ut + (size_t)r0 * L_IN;   // overwrite own rows (in-place reuse)
    float* y1 = g_ut + (size_t)r1 * L_IN;
    for (int l = threadIdx.x; l < L_IN; l += TH){
        float2 v = data[SM_IDX(START_OFF + l)];
        y0[l] = v.x;
        y1[l] = v.y;
    }
}

// Output transpose: g_ut[(b*D + d)*L + l] -> out(B,L,D)
__global__ void tout_kernel(float* __restrict__ out){
    __shared__ float tile[32][33];
    const int b  = blockIdx.z;
    const int l0 = blockIdx.x * 32, d0 = blockIdx.y * 32;
    const int tx = threadIdx.x, ty = threadIdx.y;
    tile[ty][tx] = g_ut[(size_t)(b * D_CH + d0 + ty) * L_IN + l0 + tx];
    __syncthreads();
    // tile[tx][ty] = g_ut[(b*D + d0+tx)][l0+ty]  -> out[b][l0+ty][d0+tx] (coalesced in tx)
    out[(size_t)b * L_IN * D_CH + (size_t)(l0 + ty) * D_CH + d0 + tx] = tile[tx][ty];
}

extern "C" void kernel_launch(void* const* d_in, const int* in_sizes, int n_in,
                              void* d_out, int out_size){
    const float* u = (const float*)d_in[0];
    const float* h = (const float*)d_in[1];
    float* out     = (float*)d_out;

    cudaFuncSetAttribute(filt_kernel, cudaFuncAttributeMaxDynamicSharedMemorySize, SMEM_BYTES);
    cudaFuncSetAttribute(conv_kernel, cudaFuncAttributeMaxDynamicSharedMemorySize, SMEM_BYTES);

    twinit_kernel<<<FFT_HN/256, 256>>>();
    filt_kernel<<<D_CH, TH, SMEM_BYTES>>>(h);
    tin_kernel<<<dim3(L_IN/32, D_CH/32, B_SZ), dim3(32, 32)>>>(u);
    conv_kernel<<<B_SZ * (D_CH/2), TH, SMEM_BYTES>>>();
    tout_kernel<<<dim3(L_IN/32, D_CH/32, B_SZ), dim3(32, 32)>>>(out);
}

// round 4
// speedup vs baseline: 1.8252x; 1.8252x over previous
#include <cuda_runtime.h>
#include <math.h>

// Problem constants
#define FFT_N   16384            // next_pow2(L + K - 1)
#define L_IN    8192
#define K_FILT  8192
#define D_CH    256
#define B_SZ    8
#define TH      512              // threads per FFT CTA
#define START_OFF 4095           // (K-1)//2
#define TW_SZ   4096             // twiddle table: W_N^k, k < N/4 (all we ever index)

// Padded shared-memory indexing (helps the q=16 fused pass; stride-1 passes unaffected)
#define SM_IDX(a) ((a) + ((a) >> 5))
#define SM_DATA_SZ (FFT_N + (FFT_N >> 5))                        // 16896 float2
#define SMEM_BYTES ((SM_DATA_SZ + TW_SZ) * (int)sizeof(float2))  // 167936 B

// Scratch (device globals; allocation-free)
__device__ float2 g_tw[TW_SZ];
__device__ __align__(16) float2 g_Hf[(size_t)D_CH * FFT_N];  // filter spectra, permuted, * (1/N)
__device__ float  g_ut[(size_t)B_SZ * D_CH * L_IN];          // row-major (B*D, L), in/out scratch

__device__ __forceinline__ float2 cadd(float2 a, float2 b){ return make_float2(a.x+b.x, a.y+b.y); }
__device__ __forceinline__ float2 csub(float2 a, float2 b){ return make_float2(a.x-b.x, a.y-b.y); }
__device__ __forceinline__ float2 cmul(float2 a, float2 b){
    return make_float2(a.x*b.x - a.y*b.y, a.x*b.y + a.y*b.x);
}
__device__ __forceinline__ float2 cmulc(float2 a, float2 b){   // a * conj(b)
    return make_float2(a.x*b.x + a.y*b.y, a.y*b.x - a.x*b.y);
}

// W_N^1024 = e^{-i*pi/8}; qq*step == N/16 == 1024 for every fused pass.
#define CW_RE 0.9238795325112867f
#define CW_IM (-0.3826834323650898f)

// ---------------- Fused radix-16 passes (two radix-4 stages in registers) ----------------
// Forward DIF pair (stage s then s+1). qq = 1<<LQQ (= q/4), step = 1<<LSTEP, q = 4*qq.
template<int LQQ, int LSTEP>
__device__ __forceinline__ void pass_fwd(float2* __restrict__ d, const float2* __restrict__ tw){
    const int qq = 1 << LQQ, q = qq << 2;
    #pragma unroll
    for (int r = 0; r < (FFT_N/16)/TH; ++r){
        int t2 = threadIdx.x + r*TH;
        int bb = t2 >> LQQ;
        int ii = t2 & (qq - 1);
        int base = bb*(q << 2) + ii;
        float2 x[4][4];
        #pragma unroll
        for (int t = 0; t < 4; ++t)
            #pragma unroll
            for (int j = 0; j < 4; ++j)
                x[t][j] = d[SM_IDX(base + t*q + j*qq)];
        // stage s: butterfly over t, twiddle W^{(ii + j*qq)*step} = w * CW^j
        float2 w = tw[ii << LSTEP];
        const float2 cw = make_float2(CW_RE, CW_IM);
        #pragma unroll
        for (int j = 0; j < 4; ++j){
            float2 t0 = cadd(x[0][j], x[2][j]), t1 = csub(x[0][j], x[2][j]);
            float2 t2c = cadd(x[1][j], x[3][j]);
            float2 u  = csub(x[1][j], x[3][j]);
            float2 t3 = make_float2(u.y, -u.x);
            float2 w2 = cmul(w, w), w3 = cmul(w2, w);
            x[0][j] = cadd(t0, t2c);
            x[1][j] = cmul(cadd(t1, t3), w);
            x[2][j] = cmul(csub(t0, t2c), w2);
            x[3][j] = cmul(csub(t1, t3), w3);
            w = cmul(w, cw);
        }
        // stage s+1: butterfly over j, twiddle W^{ii*4*step}
        float2 v = tw[ii << (LSTEP + 2)];
        float2 v2 = cmul(v, v), v3 = cmul(v2, v);
        #pragma unroll
        for (int t = 0; t < 4; ++t){
            float2 t0 = cadd(x[t][0], x[t][2]), t1 = csub(x[t][0], x[t][2]);
            float2 t2c = cadd(x[t][1], x[t][3]);
            float2 u  = csub(x[t][1], x[t][3]);
            float2 t3 = make_float2(u.y, -u.x);
            x[t][0] = cadd(t0, t2c);
            x[t][1] = cmul(cadd(t1, t3), v);
            x[t][2] = cmul(csub(t0, t2c), v2);
            x[t][3] = cmul(csub(t1, t3), v3);
        }
        #pragma unroll
        for (int t = 0; t < 4; ++t)
            #pragma unroll
            for (int j = 0; j < 4; ++j)
                d[SM_IDX(base + t*q + j*qq)] = x[t][j];
    }
    __syncthreads();
}

// Inverse DIT pair (stage s+1 then s), conjugate twiddles.
template<int LQQ, int LSTEP>
__device__ __forceinline__ void pass_inv(float2* __restrict__ d, const float2* __restrict__ tw){
    const int qq = 1 << LQQ, q = qq << 2;
    #pragma unroll
    for (int r = 0; r < (FFT_N/16)/TH; ++r){
        int t2 = threadIdx.x + r*TH;
        int bb = t2 >> LQQ;
        int ii = t2 & (qq - 1);
        int base = bb*(q << 2) + ii;
        float2 x[4][4];
        #pragma unroll
        for (int t = 0; t < 4; ++t)
            #pragma unroll
            for (int j = 0; j < 4; ++j)
                x[t][j] = d[SM_IDX(base + t*q + j*qq)];
        // stage s+1 inverse: over j
        float2 v = tw[ii << (LSTEP + 2)];
        float2 v2 = cmul(v, v), v3 = cmul(v2, v);
        #pragma unroll
        for (int t = 0; t < 4; ++t){
            float2 u1 = cmulc(x[t][1], v);
            float2 u2 = cmulc(x[t][2], v2);
            float2 u3 = cmulc(x[t][3], v3);
            float2 a  = cadd(x[t][0], u2), b = csub(x[t][0], u2);
            float2 cc = cadd(u1, u3), e = csub(u1, u3);
            float2 ie = make_float2(-e.y, e.x);
            x[t][0] = cadd(a, cc);
            x[t][1] = cadd(b, ie);
            x[t][2] = csub(a, cc);
            x[t][3] = csub(b, ie);
        }
        // stage s inverse: over t
        float2 w = tw[ii << LSTEP];
        const float2 cw = make_float2(CW_RE, CW_IM);
        #pragma unroll
        for (int j = 0; j < 4; ++j){
            float2 w2 = cmul(w, w), w3 = cmul(w2, w);
            float2 u1 = cmulc(x[1][j], w);
            float2 u2 = cmulc(x[2][j], w2);
            float2 u3 = cmulc(x[3][j], w3);
            float2 a  = cadd(x[0][j], u2), b = csub(x[0][j], u2);
            float2 cc = cadd(u1, u3), e = csub(u1, u3);
            float2 ie = make_float2(-e.y, e.x);
            x[0][j] = cadd(a, cc);
            x[1][j] = cadd(b, ie);
            x[2][j] = csub(a, cc);
            x[3][j] = csub(b, ie);
            w = cmul(w, cw);
        }
        #pragma unroll
        for (int t = 0; t < 4; ++t)
            #pragma unroll
            for (int j = 0; j < 4; ++j)
                d[SM_IDX(base + t*q + j*qq)] = x[t][j];
    }
    __syncthreads();
}

// First forward pass (stages 0,1) with the global load fused in (top half implicit zeros).
// x1g may be null (filter path: imaginary part = 0).
__device__ __forceinline__ void pass01_fwd_load(float2* __restrict__ d, const float2* __restrict__ tw,
                                                const float* __restrict__ x0g, const float* __restrict__ x1g){
    #pragma unroll
    for (int r = 0; r < 2; ++r){
        int ii = threadIdx.x + r*TH;      // 0..1023 (bb = 0)
        float2 x[4][4];
        #pragma unroll
        for (int t = 0; t < 4; ++t)
            #pragma unroll
            for (int j = 0; j < 4; ++j){
                if (t < 2){
                    int idx = t*4096 + j*1024 + ii;
                    x[t][j] = make_float2(x0g[idx], x1g ? x1g[idx] : 0.0f);
                } else {
                    x[t][j] = make_float2(0.0f, 0.0f);
                }
            }
        float2 w = tw[ii];
        const float2 cw = make_float2(CW_RE, CW_IM);
        #pragma unroll
        for (int j = 0; j < 4; ++j){
            float2 t0 = cadd(x[0][j], x[2][j]), t1 = csub(x[0][j], x[2][j]);
            float2 t2c = cadd(x[1][j], x[3][j]);
            float2 u  = csub(x[1][j], x[3][j]);
            float2 t3 = make_float2(u.y, -u.x);
            float2 w2 = cmul(w, w), w3 = cmul(w2, w);
            x[0][j] = cadd(t0, t2c);
            x[1][j] = cmul(cadd(t1, t3), w);
            x[2][j] = cmul(csub(t0, t2c), w2);
            x[3][j] = cmul(csub(t1, t3), w3);
            w = cmul(w, cw);
        }
        float2 v = tw[ii << 2];
        float2 v2 = cmul(v, v), v3 = cmul(v2, v);
        #pragma unroll
        for (int t = 0; t < 4; ++t){
            float2 t0 = cadd(x[t][0], x[t][2]), t1 = csub(x[t][0], x[t][2]);
            float2 t2c = cadd(x[t][1], x[t][3]);
            float2 u  = csub(x[t][1], x[t][3]);
            float2 t3 = make_float2(u.y, -u.x);
            x[t][0] = cadd(t0, t2c);
            x[t][1] = cmul(cadd(t1, t3), v);
            x[t][2] = cmul(csub(t0, t2c), v2);
            x[t][3] = cmul(csub(t1, t3), v3);
        }
        #pragma unroll
        for (int t = 0; t < 4; ++t)
            #pragma unroll
            for (int j = 0; j < 4; ++j)
                d[SM_IDX(t*4096 + j*1024 + ii)] = x[t][j];
    }
    __syncthreads();
}

// Last inverse pass (stages 1,0) with the windowed global store fused in.
__device__ __forceinline__ void pass10_inv_store(const float2* __restrict__ d, const float2* __restrict__ tw,
                                                 float* __restrict__ y0, float* __restrict__ y1){
    #pragma unroll
    for (int r = 0; r < 2; ++r){
        int ii = threadIdx.x + r*TH;
        float2 x[4][4];
        #pragma unroll
        for (int t = 0; t < 4; ++t)
            #pragma unroll
            for (int j = 0; j < 4; ++j)
                x[t][j] = d[SM_IDX(t*4096 + j*1024 + ii)];
        // stage 1 inverse: over j
        float2 v = tw[ii << 2];
        float2 v2 = cmul(v, v), v3 = cmul(v2, v);
        #pragma unroll
        for (int t = 0; t < 4; ++t){
            float2 u1 = cmulc(x[t][1], v);
            float2 u2 = cmulc(x[t][2], v2);
            float2 u3 = cmulc(x[t][3], v3);
            float2 a  = cadd(x[t][0], u2), b = csub(x[t][0], u2);
            float2 cc = cadd(u1, u3), e = csub(u1, u3);
            float2 ie = make_float2(-e.y, e.x);
            x[t][0] = cadd(a, cc);
            x[t][1] = cadd(b, ie);
            x[t][2] = csub(a, cc);
            x[t][3] = csub(b, ie);
        }
        // stage 0 inverse: over t
        float2 w = tw[ii];
        const float2 cw = make_float2(CW_RE, CW_IM);
        #pragma unroll
        for (int j = 0; j < 4; ++j){
            float2 w2 = cmul(w, w), w3 = cmul(w2, w);
            float2 u1 = cmulc(x[1][j], w);
            float2 u2 = cmulc(x[2][j], w2);
            float2 u3 = cmulc(x[3][j], w3);
            float2 a  = cadd(x[0][j], u2), b = csub(x[0][j], u2);
            float2 cc = cadd(u1, u3), e = csub(u1, u3);
            float2 ie = make_float2(-e.y, e.x);
            x[0][j] = cadd(a, cc);
            x[1][j] = cadd(b, ie);
            x[2][j] = csub(a, cc);
            x[3][j] = csub(b, ie);
            w = cmul(w, cw);
        }
        #pragma unroll
        for (int t = 0; t < 4; ++t)
            #pragma unroll
            for (int j = 0; j < 4; ++j){
                int p = t*4096 + j*1024 + ii;
                int l = p - START_OFF;
                if (l >= 0 && l < L_IN){
                    y0[l] = x[t][j].x;
                    y1[l] = x[t][j].y;
                }
            }
    }
}

// ---------------- Kernels ----------------
__global__ void twinit_kernel(){
    int k = blockIdx.x * blockDim.x + threadIdx.x;
    if (k < TW_SZ){
        double ang = -2.0 * M_PI * (double)k / (double)FFT_N;
        g_tw[k] = make_float2((float)cos(ang), (float)sin(ang));
    }
}

// Filter spectra: fwd FFT (same pipeline as data), stage 6 + scale + store fused.
__global__ __launch_bounds__(TH) void filt_kernel(const float* __restrict__ h){
    extern __shared__ float2 sm[];
    float2* data = sm;
    float2* stw  = sm + SM_DATA_SZ;
    const int f = blockIdx.x;
    for (int k = threadIdx.x; k < TW_SZ; k += TH) stw[k] = g_tw[k];
    __syncthreads();

    pass01_fwd_load(data, stw, h + (size_t)f * K_FILT, nullptr);
    pass_fwd<6,4>(data, stw);   // stages 2,3
    pass_fwd<2,8>(data, stw);   // stages 4,5

    // stage 6 (twiddle-free) + scale + global store
    const float sc = 1.0f / (float)FFT_N;
    float2* Hrow = g_Hf + (size_t)f * FFT_N;
    #pragma unroll
    for (int r = 0; r < (FFT_N/4)/TH; ++r){
        int k = threadIdx.x + r*TH;
        int base = 4*k;
        float2 x0 = data[SM_IDX(base)],   x1 = data[SM_IDX(base+1)];
        float2 x2 = data[SM_IDX(base+2)], x3 = data[SM_IDX(base+3)];
        float2 t0 = cadd(x0, x2), t1 = csub(x0, x2), t2 = cadd(x1, x3);
        float2 u  = csub(x1, x3);
        float2 t3 = make_float2(u.y, -u.x);
        float2 y0 = cadd(t0, t2), y1 = cadd(t1, t3), y2 = csub(t0, t2), y3 = csub(t1, t3);
        *reinterpret_cast<float4*>(Hrow + base)     = make_float4(y0.x*sc, y0.y*sc, y1.x*sc, y1.y*sc);
        *reinterpret_cast<float4*>(Hrow + base + 2) = make_float4(y2.x*sc, y2.y*sc, y3.x*sc, y3.y*sc);
    }
}

// Input transpose: u(B,L,D) -> g_ut[(b*D + d)*L + l]
__global__ void tin_kernel(const float* __restrict__ u){
    __shared__ float tile[32][33];
    const int b  = blockIdx.z;
    const int l0 = blockIdx.x * 32, d0 = blockIdx.y * 32;
    const int tx = threadIdx.x, ty = threadIdx.y;
    tile[ty][tx] = u[(size_t)b * L_IN * D_CH + (size_t)(l0 + ty) * D_CH + d0 + tx];
    __syncthreads();
    g_ut[(size_t)(b * D_CH + d0 + ty) * L_IN + l0 + tx] = tile[tx][ty];
}

// Main fused conv: 1024 CTAs. Rows (b,2m),(b,2m+1) share filter f = b*32 + m/4.
__global__ __launch_bounds__(TH) void conv_kernel(){
    extern __shared__ float2 sm[];
    float2* data = sm;
    float2* stw  = sm + SM_DATA_SZ;
    const int c  = blockIdx.x;
    const int b  = c >> 7;
    const int m  = c & 127;
    const int r0 = b * D_CH + 2*m;
    const int r1 = r0 + 1;
    const int f  = b * 32 + (m >> 2);

    for (int k = threadIdx.x; k < TW_SZ; k += TH) stw[k] = g_tw[k];
    __syncthreads();

    pass01_fwd_load(data, stw, g_ut + (size_t)r0 * L_IN, g_ut + (size_t)r1 * L_IN);
    pass_fwd<6,4>(data, stw);
    pass_fwd<2,8>(data, stw);

    // stage 6 fwd + pointwise * H + stage 6 inv, all in registers
    const float2* __restrict__ Hrow = g_Hf + (size_t)f * FFT_N;
    #pragma unroll
    for (int r = 0; r < (FFT_N/4)/TH; ++r){
        int k = threadIdx.x + r*TH;
        int base = 4*k;
        float2 x0 = data[SM_IDX(base)],   x1 = data[SM_IDX(base+1)];
        float2 x2 = data[SM_IDX(base+2)], x3 = data[SM_IDX(base+3)];
        float2 t0 = cadd(x0, x2), t1 = csub(x0, x2), t2 = cadd(x1, x3);
        float2 u  = csub(x1, x3);
        float2 t3 = make_float2(u.y, -u.x);
        float2 y0 = cadd(t0, t2), y1 = cadd(t1, t3), y2 = csub(t0, t2), y3 = csub(t1, t3);
        float4 hA = *reinterpret_cast<const float4*>(Hrow + base);
        float4 hB = *reinterpret_cast<const float4*>(Hrow + base + 2);
        y0 = cmul(y0, make_float2(hA.x, hA.y));
        y1 = cmul(y1, make_float2(hA.z, hA.w));
        y2 = cmul(y2, make_float2(hB.x, hB.y));
        y3 = cmul(y3, make_float2(hB.z, hB.w));
        float2 a  = cadd(y0, y2), bb = csub(y0, y2);
        float2 cc = cadd(y1, y3), e  = csub(y1, y3);
        float2 ie = make_float2(-e.y, e.x);
        data[SM_IDX(base)]   = cadd(a, cc);
        data[SM_IDX(base+1)] = cadd(bb, ie);
        data[SM_IDX(base+2)] = csub(a, cc);
        data[SM_IDX(base+3)] = csub(bb, ie);
    }
    __syncthreads();

    pass_inv<2,8>(data, stw);   // stages 5,4
    pass_inv<6,4>(data, stw);   // stages 3,2
    pass10_inv_store(data, stw, g_ut + (size_t)r0 * L_IN, g_ut + (size_t)r1 * L_IN);
}

// Output transpose: g_ut[(b*D + d)*L + l] -> out(B,L,D)
__global__ void tout_kernel(float* __restrict__ out){
    __shared__ float tile[32][33];
    const int b  = blockIdx.z;
    const int l0 = blockIdx.x * 32, d0 = blockIdx.y * 32;
    const int tx = threadIdx.x, ty = threadIdx.y;
    tile[ty][tx] = g_ut[(size_t)(b * D_CH + d0 + ty) * L_IN + l0 + tx];
    __syncthreads();
    out[(size_t)b * L_IN * D_CH + (size_t)(l0 + ty) * D_CH + d0 + tx] = tile[tx][ty];
}

extern "C" void kernel_launch(void* const* d_in, const int* in_sizes, int n_in,
                              void* d_out, int out_size){
    const float* u = (const float*)d_in[0];
    const float* h = (const float*)d_in[1];
    float* out     = (float*)d_out;

    cudaFuncSetAttribute(filt_kernel, cudaFuncAttributeMaxDynamicSharedMemorySize, SMEM_BYTES);
    cudaFuncSetAttribute(conv_kernel, cudaFuncAttributeMaxDynamicSharedMemorySize, SMEM_BYTES);

    twinit_kernel<<<TW_SZ/256, 256>>>();
    filt_kernel<<<D_CH, TH, SMEM_BYTES>>>(h);
    tin_kernel<<<dim3(L_IN/32, D_CH/32, B_SZ), dim3(32, 32)>>>(u);
    conv_kernel<<<B_SZ * (D_CH/2), TH, SMEM_BYTES>>>();
    tout_kernel<<<dim3(L_IN/32, D_CH/32, B_SZ), dim3(32, 32)>>>(out);
}

// round 5
// speedup vs baseline: 2.3130x; 1.2673x over previous
#include <cuda_runtime.h>
#include <math.h>

// Problem constants
#define FFT_N   16384            // next_pow2(L + K - 1)
#define L_IN    8192
#define K_FILT  8192
#define D_CH    256
#define B_SZ    8
#define TH      512              // threads per FFT CTA
#define START_OFF 4095           // (K-1)//2
#define TW_SZ   4096             // twiddle table: W_N^k, k < N/4 (all we ever index)
#define DH      (D_CH/2)         // 128 float2 per (b,l) row

// Padded shared-memory indexing
#define SM_IDX(a) ((a) + ((a) >> 5))
#define SM_DATA_SZ (FFT_N + (FFT_N >> 5))                        // 16896 float2
#define SMEM_BYTES ((SM_DATA_SZ + TW_SZ) * (int)sizeof(float2))  // 167936 B

// Scratch (device globals; allocation-free)
__device__ float2 g_tw[TW_SZ];
__device__ __align__(16) float2 g_Hf[(size_t)D_CH * FFT_N];  // filter spectra, digit-reversed, * (1/N)

__device__ __forceinline__ float2 cadd(float2 a, float2 b){ return make_float2(a.x+b.x, a.y+b.y); }
__device__ __forceinline__ float2 csub(float2 a, float2 b){ return make_float2(a.x-b.x, a.y-b.y); }
__device__ __forceinline__ float2 cmul(float2 a, float2 b){
    return make_float2(a.x*b.x - a.y*b.y, a.x*b.y + a.y*b.x);
}
__device__ __forceinline__ float2 cmulc(float2 a, float2 b){   // a * conj(b)
    return make_float2(a.x*b.x + a.y*b.y, a.y*b.x - a.x*b.y);
}
// base-4 digit reversal of a 14-bit index (7 digits)
__device__ __forceinline__ int rev4_14(int p){
    unsigned x = __brev((unsigned)p) >> 18;                 // bit-reverse 14 bits
    return (int)(((x & 0x1555u) << 1) | ((x >> 1) & 0x1555u)); // swap bit pairs
}

// W_N^1024 = e^{-i*pi/8}; qq*step == N/16 == 1024 for every fused pass.
#define CW_RE 0.9238795325112867f
#define CW_IM (-0.3826834323650898f)

// ---------------- Fused radix-16 passes (two radix-4 stages in registers) ----------------
template<int LQQ, int LSTEP>
__device__ __forceinline__ void pass_fwd(float2* __restrict__ d, const float2* __restrict__ tw){
    const int qq = 1 << LQQ, q = qq << 2;
    #pragma unroll
    for (int r = 0; r < (FFT_N/16)/TH; ++r){
        int t2 = threadIdx.x + r*TH;
        int bb = t2 >> LQQ;
        int ii = t2 & (qq - 1);
        int base = bb*(q << 2) + ii;
        float2 x[4][4];
        #pragma unroll
        for (int t = 0; t < 4; ++t)
            #pragma unroll
            for (int j = 0; j < 4; ++j)
                x[t][j] = d[SM_IDX(base + t*q + j*qq)];
        float2 w = tw[ii << LSTEP];
        const float2 cw = make_float2(CW_RE, CW_IM);
        #pragma unroll
        for (int j = 0; j < 4; ++j){
            float2 t0 = cadd(x[0][j], x[2][j]), t1 = csub(x[0][j], x[2][j]);
            float2 t2c = cadd(x[1][j], x[3][j]);
            float2 u  = csub(x[1][j], x[3][j]);
            float2 t3 = make_float2(u.y, -u.x);
            float2 w2 = cmul(w, w), w3 = cmul(w2, w);
            x[0][j] = cadd(t0, t2c);
            x[1][j] = cmul(cadd(t1, t3), w);
            x[2][j] = cmul(csub(t0, t2c), w2);
            x[3][j] = cmul(csub(t1, t3), w3);
            w = cmul(w, cw);
        }
        float2 v = tw[ii << (LSTEP + 2)];
        float2 v2 = cmul(v, v), v3 = cmul(v2, v);
        #pragma unroll
        for (int t = 0; t < 4; ++t){
            float2 t0 = cadd(x[t][0], x[t][2]), t1 = csub(x[t][0], x[t][2]);
            float2 t2c = cadd(x[t][1], x[t][3]);
            float2 u  = csub(x[t][1], x[t][3]);
            float2 t3 = make_float2(u.y, -u.x);
            x[t][0] = cadd(t0, t2c);
            x[t][1] = cmul(cadd(t1, t3), v);
            x[t][2] = cmul(csub(t0, t2c), v2);
            x[t][3] = cmul(csub(t1, t3), v3);
        }
        #pragma unroll
        for (int t = 0; t < 4; ++t)
            #pragma unroll
            for (int j = 0; j < 4; ++j)
                d[SM_IDX(base + t*q + j*qq)] = x[t][j];
    }
    __syncthreads();
}

template<int LQQ, int LSTEP>
__device__ __forceinline__ void pass_inv(float2* __restrict__ d, const float2* __restrict__ tw){
    const int qq = 1 << LQQ, q = qq << 2;
    #pragma unroll
    for (int r = 0; r < (FFT_N/16)/TH; ++r){
        int t2 = threadIdx.x + r*TH;
        int bb = t2 >> LQQ;
        int ii = t2 & (qq - 1);
        int base = bb*(q << 2) + ii;
        float2 x[4][4];
        #pragma unroll
        for (int t = 0; t < 4; ++t)
            #pragma unroll
            for (int j = 0; j < 4; ++j)
                x[t][j] = d[SM_IDX(base + t*q + j*qq)];
        float2 v = tw[ii << (LSTEP + 2)];
        float2 v2 = cmul(v, v), v3 = cmul(v2, v);
        #pragma unroll
        for (int t = 0; t < 4; ++t){
            float2 u1 = cmulc(x[t][1], v);
            float2 u2 = cmulc(x[t][2], v2);
            float2 u3 = cmulc(x[t][3], v3);
            float2 a  = cadd(x[t][0], u2), b = csub(x[t][0], u2);
            float2 cc = cadd(u1, u3), e = csub(u1, u3);
            float2 ie = make_float2(-e.y, e.x);
            x[t][0] = cadd(a, cc);
            x[t][1] = cadd(b, ie);
            x[t][2] = csub(a, cc);
            x[t][3] = csub(b, ie);
        }
        float2 w = tw[ii << LSTEP];
        const float2 cw = make_float2(CW_RE, CW_IM);
        #pragma unroll
        for (int j = 0; j < 4; ++j){
            float2 w2 = cmul(w, w), w3 = cmul(w2, w);
            float2 u1 = cmulc(x[1][j], w);
            float2 u2 = cmulc(x[2][j], w2);
            float2 u3 = cmulc(x[3][j], w3);
            float2 a  = cadd(x[0][j], u2), b = csub(x[0][j], u2);
            float2 cc = cadd(u1, u3), e = csub(u1, u3);
            float2 ie = make_float2(-e.y, e.x);
            x[0][j] = cadd(a, cc);
            x[1][j] = cadd(b, ie);
            x[2][j] = csub(a, cc);
            x[3][j] = csub(b, ie);
            w = cmul(w, cw);
        }
        #pragma unroll
        for (int t = 0; t < 4; ++t)
            #pragma unroll
            for (int j = 0; j < 4; ++j)
                d[SM_IDX(base + t*q + j*qq)] = x[t][j];
    }
    __syncthreads();
}

// Shared body for the first forward pass (stages 0,1); caller provides x[4][4] loaded.
__device__ __forceinline__ void pass01_core(float2 (&x)[4][4], int ii,
                                            float2* __restrict__ d, const float2* __restrict__ tw){
    float2 w = tw[ii];
    const float2 cw = make_float2(CW_RE, CW_IM);
    #pragma unroll
    for (int j = 0; j < 4; ++j){
        float2 t0 = cadd(x[0][j], x[2][j]), t1 = csub(x[0][j], x[2][j]);
        float2 t2c = cadd(x[1][j], x[3][j]);
        float2 u  = csub(x[1][j], x[3][j]);
        float2 t3 = make_float2(u.y, -u.x);
        float2 w2 = cmul(w, w), w3 = cmul(w2, w);
        x[0][j] = cadd(t0, t2c);
        x[1][j] = cmul(cadd(t1, t3), w);
        x[2][j] = cmul(csub(t0, t2c), w2);
        x[3][j] = cmul(csub(t1, t3), w3);
        w = cmul(w, cw);
    }
    float2 v = tw[ii << 2];
    float2 v2 = cmul(v, v), v3 = cmul(v2, v);
    #pragma unroll
    for (int t = 0; t < 4; ++t){
        float2 t0 = cadd(x[t][0], x[t][2]), t1 = csub(x[t][0], x[t][2]);
        float2 t2c = cadd(x[t][1], x[t][3]);
        float2 u  = csub(x[t][1], x[t][3]);
        float2 t3 = make_float2(u.y, -u.x);
        x[t][0] = cadd(t0, t2c);
        x[t][1] = cmul(cadd(t1, t3), v);
        x[t][2] = cmul(csub(t0, t2c), v2);
        x[t][3] = cmul(csub(t1, t3), v3);
    }
    #pragma unroll
    for (int t = 0; t < 4; ++t)
        #pragma unroll
        for (int j = 0; j < 4; ++j)
            d[SM_IDX(t*4096 + j*1024 + ii)] = x[t][j];
}

// First pass, loading two real rows (filter path): z = h0 + i*h1, top half zero.
__device__ __forceinline__ void pass01_load_rows(float2* __restrict__ d, const float2* __restrict__ tw,
                                                 const float* __restrict__ h0, const float* __restrict__ h1){
    #pragma unroll
    for (int r = 0; r < 2; ++r){
        int ii = threadIdx.x + r*TH;
        float2 x[4][4];
        #pragma unroll
        for (int t = 0; t < 4; ++t)
            #pragma unroll
            for (int j = 0; j < 4; ++j){
                if (t < 2){
                    int idx = t*4096 + j*1024 + ii;
                    x[t][j] = make_float2(h0[idx], h1[idx]);
                } else x[t][j] = make_float2(0.0f, 0.0f);
            }
        pass01_core(x, ii, d, tw);
    }
    __syncthreads();
}

// First pass, loading strided float2 directly from u (adjacent channel pair).
__device__ __forceinline__ void pass01_load_f2(float2* __restrict__ d, const float2* __restrict__ tw,
                                               const float2* __restrict__ src){
    #pragma unroll
    for (int r = 0; r < 2; ++r){
        int ii = threadIdx.x + r*TH;
        float2 x[4][4];
        #pragma unroll
        for (int t = 0; t < 4; ++t)
            #pragma unroll
            for (int j = 0; j < 4; ++j){
                if (t < 2){
                    int idx = t*4096 + j*1024 + ii;
                    x[t][j] = src[(size_t)idx * DH];
                } else x[t][j] = make_float2(0.0f, 0.0f);
            }
        pass01_core(x, ii, d, tw);
    }
    __syncthreads();
}

// Last inverse pass (stages 1,0) fused with windowed strided float2 store to out.
__device__ __forceinline__ void pass10_inv_store(const float2* __restrict__ d, const float2* __restrict__ tw,
                                                 float2* __restrict__ dst){
    #pragma unroll
    for (int r = 0; r < 2; ++r){
        int ii = threadIdx.x + r*TH;
        float2 x[4][4];
        #pragma unroll
        for (int t = 0; t < 4; ++t)
            #pragma unroll
            for (int j = 0; j < 4; ++j)
                x[t][j] = d[SM_IDX(t*4096 + j*1024 + ii)];
        float2 v = tw[ii << 2];
        float2 v2 = cmul(v, v), v3 = cmul(v2, v);
        #pragma unroll
        for (int t = 0; t < 4; ++t){
            float2 u1 = cmulc(x[t][1], v);
            float2 u2 = cmulc(x[t][2], v2);
            float2 u3 = cmulc(x[t][3], v3);
            float2 a  = cadd(x[t][0], u2), b = csub(x[t][0], u2);
            float2 cc = cadd(u1, u3), e = csub(u1, u3);
            float2 ie = make_float2(-e.y, e.x);
            x[t][0] = cadd(a, cc);
            x[t][1] = cadd(b, ie);
            x[t][2] = csub(a, cc);
            x[t][3] = csub(b, ie);
        }
        float2 w = tw[ii];
        const float2 cw = make_float2(CW_RE, CW_IM);
        #pragma unroll
        for (int j = 0; j < 4; ++j){
            float2 w2 = cmul(w, w), w3 = cmul(w2, w);
            float2 u1 = cmulc(x[1][j], w);
            float2 u2 = cmulc(x[2][j], w2);
            float2 u3 = cmulc(x[3][j], w3);
            float2 a  = cadd(x[0][j], u2), b = csub(x[0][j], u2);
            float2 cc = cadd(u1, u3), e = csub(u1, u3);
            float2 ie = make_float2(-e.y, e.x);
            x[0][j] = cadd(a, cc);
            x[1][j] = cadd(b, ie);
            x[2][j] = csub(a, cc);
            x[3][j] = csub(b, ie);
            w = cmul(w, cw);
        }
        #pragma unroll
        for (int t = 0; t < 4; ++t)
            #pragma unroll
            for (int j = 0; j < 4; ++j){
                int p = t*4096 + j*1024 + ii;
                int l = p - START_OFF;
                if (l >= 0 && l < L_IN)
                    dst[(size_t)l * DH] = x[t][j];
            }
    }
}

// ---------------- Kernels ----------------
__global__ void twinit_kernel(){
    int k = blockIdx.x * blockDim.x + threadIdx.x;
    if (k < TW_SZ){
        double ang = -2.0 * M_PI * (double)k / (double)FFT_N;
        g_tw[k] = make_float2((float)cos(ang), (float)sin(ang));
    }
}

// Filter spectra: 128 CTAs, pack filters (2g, 2g+1) into one complex FFT,
// unpack via conjugate symmetry in digit-reversed position space.
__global__ __launch_bounds__(TH) void filt_kernel(const float* __restrict__ h){
    extern __shared__ float2 sm[];
    float2* data = sm;
    float2* stw  = sm + SM_DATA_SZ;
    const int g = blockIdx.x;
    for (int k = threadIdx.x; k < TW_SZ; k += TH) stw[k] = g_tw[k];
    __syncthreads();

    pass01_load_rows(data, stw, h + (size_t)(2*g) * K_FILT, h + (size_t)(2*g+1) * K_FILT);
    pass_fwd<6,4>(data, stw);   // stages 2,3
    pass_fwd<2,8>(data, stw);   // stages 4,5

    // stage 6 (twiddle-free), in smem
    #pragma unroll
    for (int r = 0; r < (FFT_N/4)/TH; ++r){
        int k = threadIdx.x + r*TH;
        int base = 4*k;
        float2 x0 = data[SM_IDX(base)],   x1 = data[SM_IDX(base+1)];
        float2 x2 = data[SM_IDX(base+2)], x3 = data[SM_IDX(base+3)];
        float2 t0 = cadd(x0, x2), t1 = csub(x0, x2), t2 = cadd(x1, x3);
        float2 u  = csub(x1, x3);
        float2 t3 = make_float2(u.y, -u.x);
        data[SM_IDX(base)]   = cadd(t0, t2);
        data[SM_IDX(base+1)] = cadd(t1, t3);
        data[SM_IDX(base+2)] = csub(t0, t2);
        data[SM_IDX(base+3)] = csub(t1, t3);
    }
    __syncthreads();

    // Unpack: position p holds freq k=rev4(p); mirror at pm=rev4((N-k)&(N-1)).
    // H0(k) = (Z(k)+conj(Z(N-k)))/2 ; H1(k) = -i(Z(k)-conj(Z(N-k)))/2 ; fold 1/N.
    const float sc = 0.5f / (float)FFT_N;
    float2* H0 = g_Hf + (size_t)(2*g)   * FFT_N;
    float2* H1 = g_Hf + (size_t)(2*g+1) * FFT_N;
    #pragma unroll
    for (int r = 0; r < FFT_N/TH; ++r){
        int p  = threadIdx.x + r*TH;
        int k  = rev4_14(p);
        int pm = rev4_14((FFT_N - k) & (FFT_N - 1));
        float2 Zp = data[SM_IDX(p)];
        float2 Zm = data[SM_IDX(pm)];
        H0[p] = make_float2((Zp.x + Zm.x)*sc, (Zp.y - Zm.y)*sc);
        H1[p] = make_float2((Zp.y + Zm.y)*sc, (Zm.x - Zp.x)*sc);
    }
}

// Main fused conv: 1024 CTAs. CTA (b, m) convolves channels d=2m,2m+1 of batch b
// directly from u (strided float2) and writes out directly. Filter f = b*32 + m/4.
__global__ __launch_bounds__(TH) void conv_kernel(const float* __restrict__ u, float* __restrict__ out){
    extern __shared__ float2 sm[];
    float2* data = sm;
    float2* stw  = sm + SM_DATA_SZ;
    const int c  = blockIdx.x;
    const int b  = c >> 7;
    const int m  = c & 127;
    const int f  = b * 32 + (m >> 2);

    for (int k = threadIdx.x; k < TW_SZ; k += TH) stw[k] = g_tw[k];
    __syncthreads();

    const float2* src = (const float2*)u + (size_t)b * L_IN * DH + m;
    pass01_load_f2(data, stw, src);
    pass_fwd<6,4>(data, stw);
    pass_fwd<2,8>(data, stw);

    // stage 6 fwd + pointwise * H + stage 6 inv, in registers
    const float2* __restrict__ Hrow = g_Hf + (size_t)f * FFT_N;
    #pragma unroll
    for (int r = 0; r < (FFT_N/4)/TH; ++r){
        int k = threadIdx.x + r*TH;
        int base = 4*k;
        float2 x0 = data[SM_IDX(base)],   x1 = data[SM_IDX(base+1)];
        float2 x2 = data[SM_IDX(base+2)], x3 = data[SM_IDX(base+3)];
        float2 t0 = cadd(x0, x2), t1 = csub(x0, x2), t2 = cadd(x1, x3);
        float2 u2v = csub(x1, x3);
        float2 t3 = make_float2(u2v.y, -u2v.x);
        float2 y0 = cadd(t0, t2), y1 = cadd(t1, t3), y2 = csub(t0, t2), y3 = csub(t1, t3);
        float4 hA = *reinterpret_cast<const float4*>(Hrow + base);
        float4 hB = *reinterpret_cast<const float4*>(Hrow + base + 2);
        y0 = cmul(y0, make_float2(hA.x, hA.y));
        y1 = cmul(y1, make_float2(hA.z, hA.w));
        y2 = cmul(y2, make_float2(hB.x, hB.y));
        y3 = cmul(y3, make_float2(hB.z, hB.w));
        float2 a  = cadd(y0, y2), bb = csub(y0, y2);
        float2 cc = cadd(y1, y3), e  = csub(y1, y3);
        float2 ie = make_float2(-e.y, e.x);
        data[SM_IDX(base)]   = cadd(a, cc);
        data[SM_IDX(base+1)] = cadd(bb, ie);
        data[SM_IDX(base+2)] = csub(a, cc);
        data[SM_IDX(base+3)] = csub(bb, ie);
    }
    __syncthreads();

    pass_inv<2,8>(data, stw);   // stages 5,4
    pass_inv<6,4>(data, stw);   // stages 3,2
    float2* dst = (float2*)out + (size_t)b * L_IN * DH + m;
    pass10_inv_store(data, stw, dst);
}

extern "C" void kernel_launch(void* const* d_in, const int* in_sizes, int n_in,
                              void* d_out, int out_size){
    const float* u = (const float*)d_in[0];
    const float* h = (const float*)d_in[1];
    float* out     = (float*)d_out;

    cudaFuncSetAttribute(filt_kernel, cudaFuncAttributeMaxDynamicSharedMemorySize, SMEM_BYTES);
    cudaFuncSetAttribute(conv_kernel, cudaFuncAttributeMaxDynamicSharedMemorySize, SMEM_BYTES);

    twinit_kernel<<<TW_SZ/256, 256>>>();
    filt_kernel<<<D_CH/2, TH, SMEM_BYTES>>>(h);
    conv_kernel<<<B_SZ * (D_CH/2), TH, SMEM_BYTES>>>(u, out);
}

// round 6
// speedup vs baseline: 2.7633x; 1.1947x over previous
#include <cuda_runtime.h>
#include <math.h>

// Problem constants
#define FFT_N   16384            // next_pow2(L + K - 1)
#define L_IN    8192
#define K_FILT  8192
#define D_CH    256
#define B_SZ    8
#define TH      512              // threads per FFT CTA
#define START_OFF 4095           // (K-1)//2
#define DH      (D_CH/2)         // 128 float2 per (b,l) row

// Padded shared-memory indexing: pad every 16 float2.
// With this padding ALL data access patterns in the passes are bank-conflict-free.
#define SM_IDX(a) ((a) + ((a) >> 4))
#define SM_DATA_SZ (FFT_N + (FFT_N >> 4))                        // 17408 float2

// Compact per-pass twiddle tables (contiguous, stride-1 indexed -> conflict-free)
#define TW_T1    0        // W^k,       k<1024  (pass01/pass10 w)
#define TW_T4    1024     // W^{4k},    k<1024  (pass01/pass10 v)
#define TW_T16   2048     // W^{16k},   k<64    (pass<6,4> w)
#define TW_T64   2112     // W^{64k},   k<64    (pass<6,4> v)
#define TW_T256  2176     // W^{256k},  k<4     (pass<2,8> w)
#define TW_T1024 2180     // W^{1024k}, k<4     (pass<2,8> v)
#define TW_TOT   2184

#define SMEM_BYTES ((SM_DATA_SZ + TW_TOT) * (int)sizeof(float2))  // 156736 B

// Scratch (device globals; allocation-free)
__device__ float2 g_twtab[TW_TOT];
__device__ __align__(16) float2 g_Hf[(size_t)D_CH * FFT_N];  // filter spectra, digit-reversed, * (1/N)

__device__ __forceinline__ float2 cadd(float2 a, float2 b){ return make_float2(a.x+b.x, a.y+b.y); }
__device__ __forceinline__ float2 csub(float2 a, float2 b){ return make_float2(a.x-b.x, a.y-b.y); }
__device__ __forceinline__ float2 cmul(float2 a, float2 b){
    return make_float2(a.x*b.x - a.y*b.y, a.x*b.y + a.y*b.x);
}
__device__ __forceinline__ float2 cmulc(float2 a, float2 b){   // a * conj(b)
    return make_float2(a.x*b.x + a.y*b.y, a.y*b.x - a.x*b.y);
}
// base-4 digit reversal of a 14-bit index (7 digits)
__device__ __forceinline__ int rev4_14(int p){
    unsigned x = __brev((unsigned)p) >> 18;
    return (int)(((x & 0x1555u) << 1) | ((x >> 1) & 0x1555u));
}

// W_N^1024 = e^{-i*pi/8}; qq*step == N/16 == 1024 for every fused pass.
#define CW_RE 0.9238795325112867f
#define CW_IM (-0.3826834323650898f)

// ---------------- Fused radix-16 passes (two radix-4 stages in registers) ----------------
// twW[k] = W^{k*step}, twV[k] = W^{4k*step}, indexed directly by ii.
template<int LQQ>
__device__ __forceinline__ void pass_fwd(float2* __restrict__ d,
                                         const float2* __restrict__ twW,
                                         const float2* __restrict__ twV){
    const int qq = 1 << LQQ, q = qq << 2;
    #pragma unroll
    for (int r = 0; r < (FFT_N/16)/TH; ++r){
        int t2 = threadIdx.x + r*TH;
        int bb = t2 >> LQQ;
        int ii = t2 & (qq - 1);
        int base = bb*(q << 2) + ii;
        float2 x[4][4];
        #pragma unroll
        for (int t = 0; t < 4; ++t)
            #pragma unroll
            for (int j = 0; j < 4; ++j)
                x[t][j] = d[SM_IDX(base + t*q + j*qq)];
        float2 w = twW[ii];
        const float2 cw = make_float2(CW_RE, CW_IM);
        #pragma unroll
        for (int j = 0; j < 4; ++j){
            float2 t0 = cadd(x[0][j], x[2][j]), t1 = csub(x[0][j], x[2][j]);
            float2 t2c = cadd(x[1][j], x[3][j]);
            float2 u  = csub(x[1][j], x[3][j]);
            float2 t3 = make_float2(u.y, -u.x);
            float2 w2 = cmul(w, w), w3 = cmul(w2, w);
            x[0][j] = cadd(t0, t2c);
            x[1][j] = cmul(cadd(t1, t3), w);
            x[2][j] = cmul(csub(t0, t2c), w2);
            x[3][j] = cmul(csub(t1, t3), w3);
            w = cmul(w, cw);
        }
        float2 v = twV[ii];
        float2 v2 = cmul(v, v), v3 = cmul(v2, v);
        #pragma unroll
        for (int t = 0; t < 4; ++t){
            float2 t0 = cadd(x[t][0], x[t][2]), t1 = csub(x[t][0], x[t][2]);
            float2 t2c = cadd(x[t][1], x[t][3]);
            float2 u  = csub(x[t][1], x[t][3]);
            float2 t3 = make_float2(u.y, -u.x);
            x[t][0] = cadd(t0, t2c);
            x[t][1] = cmul(cadd(t1, t3), v);
            x[t][2] = cmul(csub(t0, t2c), v2);
            x[t][3] = cmul(csub(t1, t3), v3);
        }
        #pragma unroll
        for (int t = 0; t < 4; ++t)
            #pragma unroll
            for (int j = 0; j < 4; ++j)
                d[SM_IDX(base + t*q + j*qq)] = x[t][j];
    }
    __syncthreads();
}

template<int LQQ>
__device__ __forceinline__ void pass_inv(float2* __restrict__ d,
                                         const float2* __restrict__ twW,
                                         const float2* __restrict__ twV){
    const int qq = 1 << LQQ, q = qq << 2;
    #pragma unroll
    for (int r = 0; r < (FFT_N/16)/TH; ++r){
        int t2 = threadIdx.x + r*TH;
        int bb = t2 >> LQQ;
        int ii = t2 & (qq - 1);
        int base = bb*(q << 2) + ii;
        float2 x[4][4];
        #pragma unroll
        for (int t = 0; t < 4; ++t)
            #pragma unroll
            for (int j = 0; j < 4; ++j)
                x[t][j] = d[SM_IDX(base + t*q + j*qq)];
        float2 v = twV[ii];
        float2 v2 = cmul(v, v), v3 = cmul(v2, v);
        #pragma unroll
        for (int t = 0; t < 4; ++t){
            float2 u1 = cmulc(x[t][1], v);
            float2 u2 = cmulc(x[t][2], v2);
            float2 u3 = cmulc(x[t][3], v3);
            float2 a  = cadd(x[t][0], u2), b = csub(x[t][0], u2);
            float2 cc = cadd(u1, u3), e = csub(u1, u3);
            float2 ie = make_float2(-e.y, e.x);
            x[t][0] = cadd(a, cc);
            x[t][1] = cadd(b, ie);
            x[t][2] = csub(a, cc);
            x[t][3] = csub(b, ie);
        }
        float2 w = twW[ii];
        const float2 cw = make_float2(CW_RE, CW_IM);
        #pragma unroll
        for (int j = 0; j < 4; ++j){
            float2 w2 = cmul(w, w), w3 = cmul(w2, w);
            float2 u1 = cmulc(x[1][j], w);
            float2 u2 = cmulc(x[2][j], w2);
            float2 u3 = cmulc(x[3][j], w3);
            float2 a  = cadd(x[0][j], u2), b = csub(x[0][j], u2);
            float2 cc = cadd(u1, u3), e = csub(u1, u3);
            float2 ie = make_float2(-e.y, e.x);
            x[0][j] = cadd(a, cc);
            x[1][j] = cadd(b, ie);
            x[2][j] = csub(a, cc);
            x[3][j] = csub(b, ie);
            w = cmul(w, cw);
        }
        #pragma unroll
        for (int t = 0; t < 4; ++t)
            #pragma unroll
            for (int j = 0; j < 4; ++j)
                d[SM_IDX(base + t*q + j*qq)] = x[t][j];
    }
    __syncthreads();
}

// Shared body for the first forward pass (stages 0,1).
__device__ __forceinline__ void pass01_core(float2 (&x)[4][4], int ii,
                                            float2* __restrict__ d,
                                            const float2* __restrict__ twW,
                                            const float2* __restrict__ twV){
    float2 w = twW[ii];
    const float2 cw = make_float2(CW_RE, CW_IM);
    #pragma unroll
    for (int j = 0; j < 4; ++j){
        float2 t0 = cadd(x[0][j], x[2][j]), t1 = csub(x[0][j], x[2][j]);
        float2 t2c = cadd(x[1][j], x[3][j]);
        float2 u  = csub(x[1][j], x[3][j]);
        float2 t3 = make_float2(u.y, -u.x);
        float2 w2 = cmul(w, w), w3 = cmul(w2, w);
        x[0][j] = cadd(t0, t2c);
        x[1][j] = cmul(cadd(t1, t3), w);
        x[2][j] = cmul(csub(t0, t2c), w2);
        x[3][j] = cmul(csub(t1, t3), w3);
        w = cmul(w, cw);
    }
    float2 v = twV[ii];
    float2 v2 = cmul(v, v), v3 = cmul(v2, v);
    #pragma unroll
    for (int t = 0; t < 4; ++t){
        float2 t0 = cadd(x[t][0], x[t][2]), t1 = csub(x[t][0], x[t][2]);
        float2 t2c = cadd(x[t][1], x[t][3]);
        float2 u  = csub(x[t][1], x[t][3]);
        float2 t3 = make_float2(u.y, -u.x);
        x[t][0] = cadd(t0, t2c);
        x[t][1] = cmul(cadd(t1, t3), v);
        x[t][2] = cmul(csub(t0, t2c), v2);
        x[t][3] = cmul(csub(t1, t3), v3);
    }
    #pragma unroll
    for (int t = 0; t < 4; ++t)
        #pragma unroll
        for (int j = 0; j < 4; ++j)
            d[SM_IDX(t*4096 + j*1024 + ii)] = x[t][j];
}

// First pass, loading two real rows (filter path): z = h0 + i*h1, top half zero.
__device__ __forceinline__ void pass01_load_rows(float2* __restrict__ d,
                                                 const float2* __restrict__ twW,
                                                 const float2* __restrict__ twV,
                                                 const float* __restrict__ h0,
                                                 const float* __restrict__ h1){
    #pragma unroll
    for (int r = 0; r < 2; ++r){
        int ii = threadIdx.x + r*TH;
        float2 x[4][4];
        #pragma unroll
        for (int t = 0; t < 4; ++t)
            #pragma unroll
            for (int j = 0; j < 4; ++j){
                if (t < 2){
                    int idx = t*4096 + j*1024 + ii;
                    x[t][j] = make_float2(h0[idx], h1[idx]);
                } else x[t][j] = make_float2(0.0f, 0.0f);
            }
        pass01_core(x, ii, d, twW, twV);
    }
    __syncthreads();
}

// First pass, loading strided float2 directly from u (adjacent channel pair).
__device__ __forceinline__ void pass01_load_f2(float2* __restrict__ d,
                                               const float2* __restrict__ twW,
                                               const float2* __restrict__ twV,
                                               const float2* __restrict__ src){
    #pragma unroll
    for (int r = 0; r < 2; ++r){
        int ii = threadIdx.x + r*TH;
        float2 x[4][4];
        #pragma unroll
        for (int t = 0; t < 4; ++t)
            #pragma unroll
            for (int j = 0; j < 4; ++j){
                if (t < 2){
                    int idx = t*4096 + j*1024 + ii;
                    x[t][j] = src[(size_t)idx * DH];
                } else x[t][j] = make_float2(0.0f, 0.0f);
            }
        pass01_core(x, ii, d, twW, twV);
    }
    __syncthreads();
}

// Last inverse pass (stages 1,0) fused with windowed strided float2 store to out.
__device__ __forceinline__ void pass10_inv_store(const float2* __restrict__ d,
                                                 const float2* __restrict__ twW,
                                                 const float2* __restrict__ twV,
                                                 float2* __restrict__ dst){
    #pragma unroll
    for (int r = 0; r < 2; ++r){
        int ii = threadIdx.x + r*TH;
        float2 x[4][4];
        #pragma unroll
        for (int t = 0; t < 4; ++t)
            #pragma unroll
            for (int j = 0; j < 4; ++j)
                x[t][j] = d[SM_IDX(t*4096 + j*1024 + ii)];
        float2 v = twV[ii];
        float2 v2 = cmul(v, v), v3 = cmul(v2, v);
        #pragma unroll
        for (int t = 0; t < 4; ++t){
            float2 u1 = cmulc(x[t][1], v);
            float2 u2 = cmulc(x[t][2], v2);
            float2 u3 = cmulc(x[t][3], v3);
            float2 a  = cadd(x[t][0], u2), b = csub(x[t][0], u2);
            float2 cc = cadd(u1, u3), e = csub(u1, u3);
            float2 ie = make_float2(-e.y, e.x);
            x[t][0] = cadd(a, cc);
            x[t][1] = cadd(b, ie);
            x[t][2] = csub(a, cc);
            x[t][3] = csub(b, ie);
        }
        float2 w = twW[ii];
        const float2 cw = make_float2(CW_RE, CW_IM);
        #pragma unroll
        for (int j = 0; j < 4; ++j){
            float2 w2 = cmul(w, w), w3 = cmul(w2, w);
            float2 u1 = cmulc(x[1][j], w);
            float2 u2 = cmulc(x[2][j], w2);
            float2 u3 = cmulc(x[3][j], w3);
            float2 a  = cadd(x[0][j], u2), b = csub(x[0][j], u2);
            float2 cc = cadd(u1, u3), e = csub(u1, u3);
            float2 ie = make_float2(-e.y, e.x);
            x[0][j] = cadd(a, cc);
            x[1][j] = cadd(b, ie);
            x[2][j] = csub(a, cc);
            x[3][j] = csub(b, ie);
            w = cmul(w, cw);
        }
        #pragma unroll
        for (int t = 0; t < 4; ++t)
            #pragma unroll
            for (int j = 0; j < 4; ++j){
                int p = t*4096 + j*1024 + ii;
                int l = p - START_OFF;
                if (l >= 0 && l < L_IN)
                    dst[(size_t)l * DH] = x[t][j];
            }
    }
}

// ---------------- Kernels ----------------
__global__ void twinit_kernel(){
    int s = blockIdx.x * blockDim.x + threadIdx.x;
    if (s >= TW_TOT) return;
    int p;
    if      (s < TW_T4)    p = s;                      // W^k
    else if (s < TW_T16)   p = 4   * (s - TW_T4);      // W^{4k}
    else if (s < TW_T64)   p = 16  * (s - TW_T16);     // W^{16k}
    else if (s < TW_T256)  p = 64  * (s - TW_T64);     // W^{64k}
    else if (s < TW_T1024) p = 256 * (s - TW_T256);    // W^{256k}
    else                   p = 1024* (s - TW_T1024);   // W^{1024k}
    double ang = -2.0 * M_PI * (double)p / (double)FFT_N;
    g_twtab[s] = make_float2((float)cos(ang), (float)sin(ang));
}

// Filter spectra: 128 CTAs, pack filters (2g, 2g+1) into one complex FFT,
// unpack via conjugate symmetry in digit-reversed position space.
__global__ __launch_bounds__(TH) void filt_kernel(const float* __restrict__ h){
    extern __shared__ float2 sm[];
    float2* data = sm;
    float2* stw  = sm + SM_DATA_SZ;
    const int g = blockIdx.x;
    for (int k = threadIdx.x; k < TW_TOT; k += TH) stw[k] = g_twtab[k];
    __syncthreads();

    pass01_load_rows(data, stw + TW_T1, stw + TW_T4,
                     h + (size_t)(2*g) * K_FILT, h + (size_t)(2*g+1) * K_FILT);
    pass_fwd<6>(data, stw + TW_T16,  stw + TW_T64);    // stages 2,3
    pass_fwd<2>(data, stw + TW_T256, stw + TW_T1024);  // stages 4,5

    // stage 6 (twiddle-free), in smem
    #pragma unroll
    for (int r = 0; r < (FFT_N/4)/TH; ++r){
        int k = threadIdx.x + r*TH;
        int base = 4*k;
        float2 x0 = data[SM_IDX(base)],   x1 = data[SM_IDX(base+1)];
        float2 x2 = data[SM_IDX(base+2)], x3 = data[SM_IDX(base+3)];
        float2 t0 = cadd(x0, x2), t1 = csub(x0, x2), t2 = cadd(x1, x3);
        float2 u  = csub(x1, x3);
        float2 t3 = make_float2(u.y, -u.x);
        data[SM_IDX(base)]   = cadd(t0, t2);
        data[SM_IDX(base+1)] = cadd(t1, t3);
        data[SM_IDX(base+2)] = csub(t0, t2);
        data[SM_IDX(base+3)] = csub(t1, t3);
    }
    __syncthreads();

    // Unpack: position p holds freq k=rev4(p); mirror at pm=rev4((N-k)&(N-1)).
    const float sc = 0.5f / (float)FFT_N;
    float2* H0 = g_Hf + (size_t)(2*g)   * FFT_N;
    float2* H1 = g_Hf + (size_t)(2*g+1) * FFT_N;
    #pragma unroll
    for (int r = 0; r < FFT_N/TH; ++r){
        int p  = threadIdx.x + r*TH;
        int k  = rev4_14(p);
        int pm = rev4_14((FFT_N - k) & (FFT_N - 1));
        float2 Zp = data[SM_IDX(p)];
        float2 Zm = data[SM_IDX(pm)];
        H0[p] = make_float2((Zp.x + Zm.x)*sc, (Zp.y - Zm.y)*sc);
        H1[p] = make_float2((Zp.y + Zm.y)*sc, (Zm.x - Zp.x)*sc);
    }
}

// Main fused conv: 1024 CTAs. CTA (b, m) convolves channels d=2m,2m+1 of batch b
// directly from u and writes out directly. Filter f = b*32 + m/4.
__global__ __launch_bounds__(TH) void conv_kernel(const float* __restrict__ u, float* __restrict__ out){
    extern __shared__ float2 sm[];
    float2* data = sm;
    float2* stw  = sm + SM_DATA_SZ;
    const int c  = blockIdx.x;
    const int b  = c >> 7;
    const int m  = c & 127;
    const int f  = b * 32 + (m >> 2);

    for (int k = threadIdx.x; k < TW_TOT; k += TH) stw[k] = g_twtab[k];
    __syncthreads();

    const float2* src = (const float2*)u + (size_t)b * L_IN * DH + m;
    pass01_load_f2(data, stw + TW_T1, stw + TW_T4, src);
    pass_fwd<6>(data, stw + TW_T16,  stw + TW_T64);
    pass_fwd<2>(data, stw + TW_T256, stw + TW_T1024);

    // stage 6 fwd + pointwise * H + stage 6 inv, in registers
    const float2* __restrict__ Hrow = g_Hf + (size_t)f * FFT_N;
    #pragma unroll
    for (int r = 0; r < (FFT_N/4)/TH; ++r){
        int k = threadIdx.x + r*TH;
        int base = 4*k;
        float2 x0 = data[SM_IDX(base)],   x1 = data[SM_IDX(base+1)];
        float2 x2 = data[SM_IDX(base+2)], x3 = data[SM_IDX(base+3)];
        float2 t0 = cadd(x0, x2), t1 = csub(x0, x2), t2 = cadd(x1, x3);
        float2 u2v = csub(x1, x3);
        float2 t3 = make_float2(u2v.y, -u2v.x);
        float2 y0 = cadd(t0, t2), y1 = cadd(t1, t3), y2 = csub(t0, t2), y3 = csub(t1, t3);
        float4 hA = *reinterpret_cast<const float4*>(Hrow + base);
        float4 hB = *reinterpret_cast<const float4*>(Hrow + base + 2);
        y0 = cmul(y0, make_float2(hA.x, hA.y));
        y1 = cmul(y1, make_float2(hA.z, hA.w));
        y2 = cmul(y2, make_float2(hB.x, hB.y));
        y3 = cmul(y3, make_float2(hB.z, hB.w));
        float2 a  = cadd(y0, y2), bb = csub(y0, y2);
        float2 cc = cadd(y1, y3), e  = csub(y1, y3);
        float2 ie = make_float2(-e.y, e.x);
        data[SM_IDX(base)]   = cadd(a, cc);
        data[SM_IDX(base+1)] = cadd(bb, ie);
        data[SM_IDX(base+2)] = csub(a, cc);
        data[SM_IDX(base+3)] = csub(bb, ie);
    }
    __syncthreads();

    pass_inv<2>(data, stw + TW_T256, stw + TW_T1024);  // stages 5,4
    pass_inv<6>(data, stw + TW_T16,  stw + TW_T64);    // stages 3,2
    float2* dst = (float2*)out + (size_t)b * L_IN * DH + m;
    pass10_inv_store(data, stw + TW_T1, stw + TW_T4, dst);
}

extern "C" void kernel_launch(void* const* d_in, const int* in_sizes, int n_in,
                              void* d_out, int out_size){
    const float* u = (const float*)d_in[0];
    const float* h = (const float*)d_in[1];
    float* out     = (float*)d_out;

    cudaFuncSetAttribute(filt_kernel, cudaFuncAttributeMaxDynamicSharedMemorySize, SMEM_BYTES);
    cudaFuncSetAttribute(conv_kernel, cudaFuncAttributeMaxDynamicSharedMemorySize, SMEM_BYTES);

    twinit_kernel<<<(TW_TOT + 255)/256, 256>>>();
    filt_kernel<<<D_CH/2, TH, SMEM_BYTES>>>(h);
    conv_kernel<<<B_SZ * (D_CH/2), TH, SMEM_BYTES>>>(u, out);
}